// round 9
// baseline (speedup 1.0000x reference)
#include <cuda_runtime.h>

#define BB 256
#define TT 256
#define DD 128
#define HHH 256

// ---------------- scratch (device globals; no allocations) ----------------
__device__ float g_xproj_enc[(size_t)BB * TT * 4 * HHH];  // 256 MB
__device__ float g_xproj_dec[(size_t)BB * TT * 4 * DD];   // 128 MB
__device__ float g_enc_out[(size_t)BB * TT * HHH];        // 64 MB
__device__ float g_hbuf_enc[2][BB][HHH];
__device__ float g_hbuf_dec[2][BB][DD];
__device__ int g_ctr_enc[TT];
__device__ int g_ctr_dec[TT];

// ---------------- init: zero h0 buffers + barrier counters ----------------
__global__ void init_kernel() {
    int tid = blockIdx.x * blockDim.x + threadIdx.x;
    int stride = gridDim.x * blockDim.x;
    float* he = &g_hbuf_enc[0][0][0];
    float* hd = &g_hbuf_dec[0][0][0];
    for (int i = tid; i < 2 * BB * HHH; i += stride) he[i] = 0.f;
    for (int i = tid; i < 2 * BB * DD; i += stride) hd[i] = 0.f;
    if (tid < TT) { g_ctr_enc[tid] = 0; g_ctr_dec[tid] = 0; }
}

// ---------------- input-projection GEMM: C[M,N] = A[M,K] @ W[N,K]^T + b1 + b2
// M = 65536, tiles 64x64, BK=16, 256 threads, 4x4 micro-tile.
template <int K>
__global__ __launch_bounds__(256) void proj_kernel(
    const float* __restrict__ Ain, const float* __restrict__ W,
    const float* __restrict__ b1, const float* __restrict__ b2,
    int src_sel, int dst_sel, int N)
{
    const float* A = src_sel ? (const float*)g_enc_out : Ain;
    float* C = dst_sel ? (float*)g_xproj_dec : (float*)g_xproj_enc;

    __shared__ float As[16][64];
    __shared__ float Bs[16][64];
    int tid = threadIdx.x;
    int bn = blockIdx.x, bm = blockIdx.y;
    int r0 = (tid >> 4) << 2;       // 0..60
    int c0 = (tid & 15) << 2;       // 0..60
    int lm = tid >> 2;              // 0..63
    int lk = (tid & 3) << 2;        // 0,4,8,12

    const float* Ag = A + (size_t)(bm * 64 + lm) * K + lk;
    const float* Wg = W + (size_t)(bn * 64 + lm) * K + lk;

    float acc[4][4];
#pragma unroll
    for (int i = 0; i < 4; ++i)
#pragma unroll
        for (int j = 0; j < 4; ++j) acc[i][j] = 0.f;

    for (int kb = 0; kb < K; kb += 16) {
        float4 av = *(const float4*)(Ag + kb);
        float4 wv = *(const float4*)(Wg + kb);
        __syncthreads();
        As[lk + 0][lm] = av.x; As[lk + 1][lm] = av.y;
        As[lk + 2][lm] = av.z; As[lk + 3][lm] = av.w;
        Bs[lk + 0][lm] = wv.x; Bs[lk + 1][lm] = wv.y;
        Bs[lk + 2][lm] = wv.z; Bs[lk + 3][lm] = wv.w;
        __syncthreads();
#pragma unroll
        for (int kk = 0; kk < 16; ++kk) {
            float4 a = *(const float4*)&As[kk][r0];
            float4 w = *(const float4*)&Bs[kk][c0];
            float ar[4] = {a.x, a.y, a.z, a.w};
            float wr[4] = {w.x, w.y, w.z, w.w};
#pragma unroll
            for (int i = 0; i < 4; ++i)
#pragma unroll
                for (int j = 0; j < 4; ++j)
                    acc[i][j] = fmaf(ar[i], wr[j], acc[i][j]);
        }
    }
    int col = bn * 64 + c0;
    float4 v1 = *(const float4*)&b1[col];
    float4 v2 = *(const float4*)&b2[col];
    float bx = v1.x + v2.x, by = v1.y + v2.y, bz = v1.z + v2.z, bw = v1.w + v2.w;
#pragma unroll
    for (int i = 0; i < 4; ++i) {
        float4 o;
        o.x = acc[i][0] + bx; o.y = acc[i][1] + by;
        o.z = acc[i][2] + bz; o.w = acc[i][3] + bw;
        *(float4*)&C[(size_t)(bm * 64 + r0 + i) * N + col] = o;
    }
}

// ---------------- grid step-barrier (all 128 CTAs co-resident) -----------
__device__ __forceinline__ void step_barrier(int* ctr, int tid) {
    __threadfence();
    __syncthreads();
    if (tid == 0) {
        atomicAdd(ctr, 1);
        while (*(volatile int*)ctr < 128) __nanosleep(32);
        __threadfence();
    }
    __syncthreads();
}

// ---------------- encoder recurrence: persistent, 128 CTAs ----------------
// CTA = 64 batch rows x 8 neurons (32 gate-cols). Whh slice in smem once.
// smem carve (floats): Ws 256x32 = 8192, Hs 64x260 = 16640, Gs 64x33 = 2112, Cs 64x8 = 512
#define ENC_SMEM_BYTES ((8192 + 16640 + 2112 + 512) * 4)

__global__ __launch_bounds__(256) void enc_rec_kernel(const float* __restrict__ Whh)
{
    extern __shared__ float sm[];
    float (*Ws)[32]  = (float(*)[32])sm;
    float (*Hs)[260] = (float(*)[260])(sm + 8192);
    float (*Gs)[33]  = (float(*)[33])(sm + 8192 + 16640);
    float (*Cs)[8]   = (float(*)[8])(sm + 8192 + 16640 + 2112);

    int tid = threadIdx.x;
    int slice = blockIdx.x & 31;   // 0..31 (neuron slices of 8)
    int btile = blockIdx.x >> 5;   // 0..3  (batch tiles of 64)
    int b0 = btile * 64;
    int j0 = slice * 8;

    // load Whh slice transposed: Ws[k][c], c = gate*8 + jj
    {
        int c = tid & 31;
        int k0 = (tid >> 5) << 5;
        int grow = (c >> 3) * HHH + j0 + (c & 7);
        const float* src = Whh + (size_t)grow * HHH + k0;
#pragma unroll
        for (int kk = 0; kk < 32; ++kk) Ws[k0 + kk][c] = src[kk];
    }
    for (int i = tid; i < 512; i += 256) ((float*)Cs)[i] = 0.f;
    __syncthreads();

    const int tr2 = (tid >> 3) << 1;                     // row pair 0..62
    const int tc4 = (tid & 7) << 2;                      // col quad 0..28
    const int gci = (tc4 >> 3) * HHH + j0 + (tc4 & 7);   // global gate col
    const float* hr0 = &Hs[tr2][0];
    const float* hr1 = &Hs[tr2 + 1][0];
    const float* wcol = &Ws[0][tc4];

    for (int t = 0; t < TT; ++t) {
        { // stage h_prev tile [64][256] from global double buffer
            int r = tid >> 2;
            int k0 = (tid & 3) << 6;
            const float* hp = &g_hbuf_enc[t & 1][b0 + r][k0];
            float* dst = &Hs[r][k0];
#pragma unroll
            for (int kk = 0; kk < 64; kk += 4)
                *(float4*)(dst + kk) = *(const float4*)(hp + kk);
        }
        __syncthreads();

        const float* xp0 = &g_xproj_enc[((size_t)(b0 + tr2) * TT + t) * 1024 + gci];
        float4 a0 = *(const float4*)xp0;
        float4 a1 = *(const float4*)(xp0 + (size_t)TT * 1024);
#pragma unroll 8
        for (int k = 0; k < HHH; ++k) {
            float h0 = hr0[k], h1 = hr1[k];
            float4 w = *(const float4*)(wcol + (k << 5));
            a0.x = fmaf(h0, w.x, a0.x); a0.y = fmaf(h0, w.y, a0.y);
            a0.z = fmaf(h0, w.z, a0.z); a0.w = fmaf(h0, w.w, a0.w);
            a1.x = fmaf(h1, w.x, a1.x); a1.y = fmaf(h1, w.y, a1.y);
            a1.z = fmaf(h1, w.z, a1.z); a1.w = fmaf(h1, w.w, a1.w);
        }
        Gs[tr2][tc4 + 0] = a0.x; Gs[tr2][tc4 + 1] = a0.y;
        Gs[tr2][tc4 + 2] = a0.z; Gs[tr2][tc4 + 3] = a0.w;
        Gs[tr2 + 1][tc4 + 0] = a1.x; Gs[tr2 + 1][tc4 + 1] = a1.y;
        Gs[tr2 + 1][tc4 + 2] = a1.z; Gs[tr2 + 1][tc4 + 3] = a1.w;
        __syncthreads();

#pragma unroll
        for (int p = tid; p < 512; p += 256) {
            int r = p >> 3, j = p & 7;
            float vi = Gs[r][j], vf = Gs[r][8 + j], vg = Gs[r][16 + j], vo = Gs[r][24 + j];
            float si = 1.f / (1.f + __expf(-vi));
            float sf = 1.f / (1.f + __expf(-vf));
            float tg = tanhf(vg);
            float so = 1.f / (1.f + __expf(-vo));
            float cv = fmaf(sf, Cs[r][j], si * tg);
            Cs[r][j] = cv;
            float h = so * tanhf(cv);
            g_hbuf_enc[(t + 1) & 1][b0 + r][j0 + j] = h;
            g_enc_out[((size_t)(b0 + r) * TT + t) * HHH + j0 + j] = h;
        }
        step_barrier(&g_ctr_enc[t], tid);
    }
}

// ---------------- decoder recurrence: 128 CTAs, 64 rows x 4 neurons ------
__global__ __launch_bounds__(256) void dec_rec_kernel(
    const float* __restrict__ Whh, float* __restrict__ out)
{
    __shared__ float Ws[128][16];
    __shared__ float Hs[64][132];
    __shared__ float Gs[64][17];
    __shared__ float Cs[64][4];

    int tid = threadIdx.x;
    int slice = blockIdx.x & 31;   // 0..31 (neuron slices of 4)
    int btile = blockIdx.x >> 5;   // 0..3
    int b0 = btile * 64;
    int j0 = slice * 4;

    {
        int c = tid & 15;
        int k0 = (tid >> 4) << 3;
        int grow = (c >> 2) * DD + j0 + (c & 3);
        const float* src = Whh + (size_t)grow * DD + k0;
#pragma unroll
        for (int kk = 0; kk < 8; ++kk) Ws[k0 + kk][c] = src[kk];
    }
    if (tid < 256) ((float*)Cs)[tid] = 0.f;
    __syncthreads();

    const int tr2 = (tid >> 3) << 1;
    const int tc2 = (tid & 7) << 1;
    const int gci = (tc2 >> 2) * DD + j0 + (tc2 & 3);
    const float* hr0 = &Hs[tr2][0];
    const float* hr1 = &Hs[tr2 + 1][0];
    const float* wcol = &Ws[0][tc2];

    for (int t = 0; t < TT; ++t) {
        {
            int r = tid >> 2;
            int k0 = (tid & 3) << 5;
            const float* hp = &g_hbuf_dec[t & 1][b0 + r][k0];
            float* dst = &Hs[r][k0];
#pragma unroll
            for (int kk = 0; kk < 32; kk += 4)
                *(float4*)(dst + kk) = *(const float4*)(hp + kk);
        }
        __syncthreads();

        const float* xp0 = &g_xproj_dec[((size_t)(b0 + tr2) * TT + t) * 512 + gci];
        float2 a0 = *(const float2*)xp0;
        float2 a1 = *(const float2*)(xp0 + (size_t)TT * 512);
#pragma unroll 8
        for (int k = 0; k < DD; ++k) {
            float h0 = hr0[k], h1 = hr1[k];
            float2 w = *(const float2*)(wcol + (k << 4));
            a0.x = fmaf(h0, w.x, a0.x); a0.y = fmaf(h0, w.y, a0.y);
            a1.x = fmaf(h1, w.x, a1.x); a1.y = fmaf(h1, w.y, a1.y);
        }
        Gs[tr2][tc2] = a0.x; Gs[tr2][tc2 + 1] = a0.y;
        Gs[tr2 + 1][tc2] = a1.x; Gs[tr2 + 1][tc2 + 1] = a1.y;
        __syncthreads();

        {
            int r = tid >> 2, j = tid & 3;
            float vi = Gs[r][j], vf = Gs[r][4 + j], vg = Gs[r][8 + j], vo = Gs[r][12 + j];
            float si = 1.f / (1.f + __expf(-vi));
            float sf = 1.f / (1.f + __expf(-vf));
            float tg = tanhf(vg);
            float so = 1.f / (1.f + __expf(-vo));
            float cv = fmaf(sf, Cs[r][j], si * tg);
            Cs[r][j] = cv;
            float h = so * tanhf(cv);
            g_hbuf_dec[(t + 1) & 1][b0 + r][j0 + j] = h;
            out[((size_t)(b0 + r) * TT + t) * DD + j0 + j] = h;
        }
        step_barrier(&g_ctr_dec[t], tid);
    }
}

// ---------------- launch ----------------
extern "C" void kernel_launch(void* const* d_in, const int* in_sizes, int n_in,
                              void* d_out, int out_size) {
    const float* x    = (const float*)d_in[0];
    const float* eWih = (const float*)d_in[1];
    const float* eWhh = (const float*)d_in[2];
    const float* ebih = (const float*)d_in[3];
    const float* ebhh = (const float*)d_in[4];
    const float* dWih = (const float*)d_in[5];
    const float* dWhh = (const float*)d_in[6];
    const float* dbih = (const float*)d_in[7];
    const float* dbhh = (const float*)d_in[8];
    float* out = (float*)d_out;

    cudaFuncSetAttribute(enc_rec_kernel,
                         cudaFuncAttributeMaxDynamicSharedMemorySize, ENC_SMEM_BYTES);

    init_kernel<<<64, 256>>>();
    // x_proj_enc = x @ eWih^T + ebih + ebhh : M=65536, N=1024, K=128
    proj_kernel<128><<<dim3(16, 1024), 256>>>(x, eWih, ebih, ebhh, 0, 0, 1024);
    enc_rec_kernel<<<128, 256, ENC_SMEM_BYTES>>>(eWhh);
    // x_proj_dec = encoded @ dWih^T + dbih + dbhh : M=65536, N=512, K=256
    proj_kernel<256><<<dim3(8, 1024), 256>>>(nullptr, dWih, dbih, dbhh, 1, 1, 512);
    dec_rec_kernel<<<128, 256>>>(dWhh, out);
}

// round 11
// speedup vs baseline: 1.0701x; 1.0701x over previous
#include <cuda_runtime.h>

#define BB 256
#define TT 256
#define DD 128
#define HHH 256

typedef unsigned long long u64t;
typedef unsigned int u32t;

// Blackwell packed fp32 ops (PTX-only; ptxas won't emit FFMA2 from C++)
#define FMA2(d,a,b,c) asm("fma.rn.f32x2 %0, %1, %2, %3;" : "=l"(d) : "l"(a), "l"(b), "l"(c))
#define PACK1(d,x)    asm("mov.b64 %0, {%1, %1};" : "=l"(d) : "r"(x))
#define UNPK(lo,hi,v) asm("mov.b64 {%0, %1}, %2;" : "=r"(lo), "=r"(hi) : "l"(v))

// ---------------- scratch (device globals; no allocations) ----------------
__device__ float g_xproj_enc[(size_t)BB * TT * 4 * HHH];  // 256 MB
__device__ float g_xproj_dec[(size_t)BB * TT * 4 * DD];   // 128 MB
__device__ float g_enc_out[(size_t)BB * TT * HHH];        // 64 MB
__device__ float g_hbuf_enc[2][BB][HHH];
__device__ float g_hbuf_dec[2][BB][DD];
__device__ int g_ctr_enc[TT][4];   // per-step, per-btile (32-CTA groups)
__device__ int g_ctr_dec[TT][4];

// ---------------- init: zero h0 buffers + barrier counters ----------------
__global__ void init_kernel() {
    int tid = blockIdx.x * blockDim.x + threadIdx.x;
    int stride = gridDim.x * blockDim.x;
    float* he = &g_hbuf_enc[0][0][0];
    float* hd = &g_hbuf_dec[0][0][0];
    for (int i = tid; i < 2 * BB * HHH; i += stride) he[i] = 0.f;
    for (int i = tid; i < 2 * BB * DD; i += stride) hd[i] = 0.f;
    int* ce = &g_ctr_enc[0][0];
    int* cd = &g_ctr_dec[0][0];
    for (int i = tid; i < TT * 4; i += stride) { ce[i] = 0; cd[i] = 0; }
}

// ---------------- input-projection GEMM: C[M,N] = A[M,K] @ W[N,K]^T + b1 + b2
// 128x128 tiles, BK=8, 256 threads, 8x8 micro-tile, packed f32x2 FMA.
template <int K>
__global__ __launch_bounds__(256) void proj_kernel(
    const float* __restrict__ Ain, const float* __restrict__ W,
    const float* __restrict__ b1, const float* __restrict__ b2,
    int src_sel, int dst_sel, int N)
{
    const float* A = src_sel ? (const float*)g_enc_out : Ain;
    float* C = dst_sel ? (float*)g_xproj_dec : (float*)g_xproj_enc;

    __shared__ float As[8][128];
    __shared__ float Bs[8][128];
    int tid = threadIdx.x;
    int bn = blockIdx.x, bm = blockIdx.y;
    int tr = tid >> 4, tc = tid & 15;   // 16x16 thread grid
    int lr = tid >> 1;                  // stage row 0..127
    int lk = (tid & 1) << 2;            // 0 or 4

    const float* Ag = A + (size_t)(bm * 128 + lr) * K + lk;
    const float* Wg = W + (size_t)(bn * 128 + lr) * K + lk;

    u64t acc[8][4];
#pragma unroll
    for (int i = 0; i < 8; ++i)
#pragma unroll
        for (int j = 0; j < 4; ++j) acc[i][j] = 0ULL;

    for (int kb = 0; kb < K; kb += 8) {
        float4 av = *(const float4*)(Ag + kb);
        float4 wv = *(const float4*)(Wg + kb);
        __syncthreads();
        As[lk + 0][lr] = av.x; As[lk + 1][lr] = av.y;
        As[lk + 2][lr] = av.z; As[lk + 3][lr] = av.w;
        Bs[lk + 0][lr] = wv.x; Bs[lk + 1][lr] = wv.y;
        Bs[lk + 2][lr] = wv.z; Bs[lk + 3][lr] = wv.w;
        __syncthreads();
#pragma unroll
        for (int kk = 0; kk < 8; ++kk) {
            float4 alo = *(const float4*)&As[kk][tr * 4];
            float4 ahi = *(const float4*)&As[kk][64 + tr * 4];
            ulonglong2 wlo = *(const ulonglong2*)&Bs[kk][tc * 4];
            ulonglong2 whi = *(const ulonglong2*)&Bs[kk][64 + tc * 4];
            float ar[8] = {alo.x, alo.y, alo.z, alo.w, ahi.x, ahi.y, ahi.z, ahi.w};
#pragma unroll
            for (int i = 0; i < 8; ++i) {
                u64t a2; PACK1(a2, __float_as_uint(ar[i]));
                FMA2(acc[i][0], a2, wlo.x, acc[i][0]);
                FMA2(acc[i][1], a2, wlo.y, acc[i][1]);
                FMA2(acc[i][2], a2, whi.x, acc[i][2]);
                FMA2(acc[i][3], a2, whi.y, acc[i][3]);
            }
        }
    }
    int c_lo = bn * 128 + tc * 4;
    int c_hi = c_lo + 64;
    float4 v1 = *(const float4*)&b1[c_lo];
    float4 v2 = *(const float4*)&b2[c_lo];
    float4 blo = make_float4(v1.x + v2.x, v1.y + v2.y, v1.z + v2.z, v1.w + v2.w);
    float4 u1 = *(const float4*)&b1[c_hi];
    float4 u2 = *(const float4*)&b2[c_hi];
    float4 bhi = make_float4(u1.x + u2.x, u1.y + u2.y, u1.z + u2.z, u1.w + u2.w);
#pragma unroll
    for (int i = 0; i < 8; ++i) {
        int row = bm * 128 + (i < 4 ? tr * 4 + i : 64 + tr * 4 + (i - 4));
        u32t l0, h0, l1, h1;
        UNPK(l0, h0, acc[i][0]); UNPK(l1, h1, acc[i][1]);
        float4 o0 = make_float4(__uint_as_float(l0) + blo.x, __uint_as_float(h0) + blo.y,
                                __uint_as_float(l1) + blo.z, __uint_as_float(h1) + blo.w);
        *(float4*)&C[(size_t)row * N + c_lo] = o0;
        UNPK(l0, h0, acc[i][2]); UNPK(l1, h1, acc[i][3]);
        float4 o1 = make_float4(__uint_as_float(l0) + bhi.x, __uint_as_float(h0) + bhi.y,
                                __uint_as_float(l1) + bhi.z, __uint_as_float(h1) + bhi.w);
        *(float4*)&C[(size_t)row * N + c_hi] = o1;
    }
}

// ---------------- encoder recurrence: persistent, 128 CTAs ----------------
// CTA = 64 batch rows x 8 neurons (32 gate-cols). Whh slice in smem once.
// Barrier only among the 32 CTAs sharing a batch tile.
#define ENC_SMEM_BYTES ((8192 + 16640 + 2112 + 512) * 4)

__global__ __launch_bounds__(256) void enc_rec_kernel(const float* __restrict__ Whh)
{
    extern __shared__ float sm[];
    float (*Ws)[32]  = (float(*)[32])sm;
    float (*Hs)[260] = (float(*)[260])(sm + 8192);
    float (*Gs)[33]  = (float(*)[33])(sm + 8192 + 16640);
    float (*Cs)[8]   = (float(*)[8])(sm + 8192 + 16640 + 2112);

    int tid = threadIdx.x;
    int slice = blockIdx.x & 31;   // 0..31 (neuron slices of 8)
    int btile = blockIdx.x >> 5;   // 0..3  (batch tiles of 64)
    int b0 = btile * 64;
    int j0 = slice * 8;

    // load Whh slice transposed: Ws[k][c], c = gate*8 + jj
    {
        int c = tid & 31;
        int k0 = (tid >> 5) << 5;
        int grow = (c >> 3) * HHH + j0 + (c & 7);
        const float* src = Whh + (size_t)grow * HHH + k0;
#pragma unroll
        for (int kk = 0; kk < 32; ++kk) Ws[k0 + kk][c] = src[kk];
    }
    for (int i = tid; i < 512; i += 256) ((float*)Cs)[i] = 0.f;
    __syncthreads();

    const int tr2 = (tid >> 3) << 1;                     // row pair 0..62
    const int tc4 = (tid & 7) << 2;                      // col quad 0..28
    const int gci = (tc4 >> 3) * HHH + j0 + (tc4 & 7);   // global gate col
    const float* hr0 = &Hs[tr2][0];
    const float* hr1 = &Hs[tr2 + 1][0];
    const float* wcol = &Ws[0][tc4];

    for (int t = 0; t < TT; ++t) {
        { // stage h_prev tile [64][256] from global double buffer
            int r = tid >> 2;
            int k0 = (tid & 3) << 6;
            const float* hp = &g_hbuf_enc[t & 1][b0 + r][k0];
            float* dst = &Hs[r][k0];
#pragma unroll
            for (int kk = 0; kk < 64; kk += 4)
                *(float4*)(dst + kk) = *(const float4*)(hp + kk);
        }
        __syncthreads();

        const float* xp0 = &g_xproj_enc[((size_t)(b0 + tr2) * TT + t) * 1024 + gci];
        ulonglong2 q0 = *(const ulonglong2*)xp0;
        ulonglong2 q1 = *(const ulonglong2*)(xp0 + (size_t)TT * 1024);
        u64t A00 = q0.x, A01 = q0.y, A10 = q1.x, A11 = q1.y;
#pragma unroll 8
        for (int k = 0; k < HHH; ++k) {
            u64t H0, H1;
            PACK1(H0, __float_as_uint(hr0[k]));
            PACK1(H1, __float_as_uint(hr1[k]));
            ulonglong2 w = *(const ulonglong2*)(wcol + (k << 5));
            FMA2(A00, H0, w.x, A00); FMA2(A01, H0, w.y, A01);
            FMA2(A10, H1, w.x, A10); FMA2(A11, H1, w.y, A11);
        }
        {
            u32t l, h;
            UNPK(l, h, A00); Gs[tr2][tc4 + 0] = __uint_as_float(l); Gs[tr2][tc4 + 1] = __uint_as_float(h);
            UNPK(l, h, A01); Gs[tr2][tc4 + 2] = __uint_as_float(l); Gs[tr2][tc4 + 3] = __uint_as_float(h);
            UNPK(l, h, A10); Gs[tr2 + 1][tc4 + 0] = __uint_as_float(l); Gs[tr2 + 1][tc4 + 1] = __uint_as_float(h);
            UNPK(l, h, A11); Gs[tr2 + 1][tc4 + 2] = __uint_as_float(l); Gs[tr2 + 1][tc4 + 3] = __uint_as_float(h);
        }
        __syncthreads();

        float hsave[2];
#pragma unroll
        for (int q = 0; q < 2; ++q) {
            int p = tid + q * 256;
            int r = p >> 3, j = p & 7;
            float vi = Gs[r][j], vf = Gs[r][8 + j], vg = Gs[r][16 + j], vo = Gs[r][24 + j];
            float si = 1.f / (1.f + __expf(-vi));
            float sf = 1.f / (1.f + __expf(-vf));
            float tg = tanhf(vg);
            float so = 1.f / (1.f + __expf(-vo));
            float cv = fmaf(sf, Cs[r][j], si * tg);
            Cs[r][j] = cv;
            float h = so * tanhf(cv);
            g_hbuf_enc[(t + 1) & 1][b0 + r][j0 + j] = h;
            hsave[q] = h;
        }
        __threadfence();
        __syncthreads();
        int* ctr = &g_ctr_enc[t][btile];
        if (tid == 0) atomicAdd(ctr, 1);
        // deferred enc_out stores overlap with the spin
#pragma unroll
        for (int q = 0; q < 2; ++q) {
            int p = tid + q * 256;
            int r = p >> 3, j = p & 7;
            g_enc_out[((size_t)(b0 + r) * TT + t) * HHH + j0 + j] = hsave[q];
        }
        if (tid == 0) {
            while (*(volatile int*)ctr < 32) __nanosleep(32);
            __threadfence();
        }
        __syncthreads();
    }
}

// ---------------- decoder recurrence: 128 CTAs, 64 rows x 4 neurons ------
__global__ __launch_bounds__(256) void dec_rec_kernel(
    const float* __restrict__ Whh, float* __restrict__ out)
{
    __shared__ float Ws[128][16];
    __shared__ float Hs[64][132];
    __shared__ float Gs[64][17];
    __shared__ float Cs[64][4];

    int tid = threadIdx.x;
    int slice = blockIdx.x & 31;   // 0..31 (neuron slices of 4)
    int btile = blockIdx.x >> 5;   // 0..3
    int b0 = btile * 64;
    int j0 = slice * 4;

    {
        int c = tid & 15;
        int k0 = (tid >> 4) << 3;
        int grow = (c >> 2) * DD + j0 + (c & 3);
        const float* src = Whh + (size_t)grow * DD + k0;
#pragma unroll
        for (int kk = 0; kk < 8; ++kk) Ws[k0 + kk][c] = src[kk];
    }
    if (tid < 256) ((float*)Cs)[tid] = 0.f;
    __syncthreads();

    const int tr2 = (tid >> 3) << 1;
    const int tc2 = (tid & 7) << 1;
    const int gci = (tc2 >> 2) * DD + j0 + (tc2 & 3);
    const float* hr0 = &Hs[tr2][0];
    const float* hr1 = &Hs[tr2 + 1][0];
    const float* wcol = &Ws[0][tc2];

    for (int t = 0; t < TT; ++t) {
        {
            int r = tid >> 2;
            int k0 = (tid & 3) << 5;
            const float* hp = &g_hbuf_dec[t & 1][b0 + r][k0];
            float* dst = &Hs[r][k0];
#pragma unroll
            for (int kk = 0; kk < 32; kk += 4)
                *(float4*)(dst + kk) = *(const float4*)(hp + kk);
        }
        __syncthreads();

        const float* xp0 = &g_xproj_dec[((size_t)(b0 + tr2) * TT + t) * 512 + gci];
        u64t A0 = *(const u64t*)xp0;
        u64t A1 = *(const u64t*)(xp0 + (size_t)TT * 512);
#pragma unroll 8
        for (int k = 0; k < DD; ++k) {
            u64t H0, H1;
            PACK1(H0, __float_as_uint(hr0[k]));
            PACK1(H1, __float_as_uint(hr1[k]));
            u64t w = *(const u64t*)(wcol + (k << 4));
            FMA2(A0, H0, w, A0);
            FMA2(A1, H1, w, A1);
        }
        {
            u32t l, h;
            UNPK(l, h, A0); Gs[tr2][tc2] = __uint_as_float(l); Gs[tr2][tc2 + 1] = __uint_as_float(h);
            UNPK(l, h, A1); Gs[tr2 + 1][tc2] = __uint_as_float(l); Gs[tr2 + 1][tc2 + 1] = __uint_as_float(h);
        }
        __syncthreads();

        float hsave;
        int r = tid >> 2, j = tid & 3;
        {
            float vi = Gs[r][j], vf = Gs[r][4 + j], vg = Gs[r][8 + j], vo = Gs[r][12 + j];
            float si = 1.f / (1.f + __expf(-vi));
            float sf = 1.f / (1.f + __expf(-vf));
            float tg = tanhf(vg);
            float so = 1.f / (1.f + __expf(-vo));
            float cv = fmaf(sf, Cs[r][j], si * tg);
            Cs[r][j] = cv;
            hsave = so * tanhf(cv);
            g_hbuf_dec[(t + 1) & 1][b0 + r][j0 + j] = hsave;
        }
        __threadfence();
        __syncthreads();
        int* ctr = &g_ctr_dec[t][btile];
        if (tid == 0) atomicAdd(ctr, 1);
        out[((size_t)(b0 + r) * TT + t) * DD + j0 + j] = hsave;
        if (tid == 0) {
            while (*(volatile int*)ctr < 32) __nanosleep(32);
            __threadfence();
        }
        __syncthreads();
    }
}

// ---------------- launch ----------------
extern "C" void kernel_launch(void* const* d_in, const int* in_sizes, int n_in,
                              void* d_out, int out_size) {
    const float* x    = (const float*)d_in[0];
    const float* eWih = (const float*)d_in[1];
    const float* eWhh = (const float*)d_in[2];
    const float* ebih = (const float*)d_in[3];
    const float* ebhh = (const float*)d_in[4];
    const float* dWih = (const float*)d_in[5];
    const float* dWhh = (const float*)d_in[6];
    const float* dbih = (const float*)d_in[7];
    const float* dbhh = (const float*)d_in[8];
    float* out = (float*)d_out;

    cudaFuncSetAttribute(enc_rec_kernel,
                         cudaFuncAttributeMaxDynamicSharedMemorySize, ENC_SMEM_BYTES);

    init_kernel<<<64, 256>>>();
    // x_proj_enc = x @ eWih^T + ebih + ebhh : M=65536, N=1024, K=128
    proj_kernel<128><<<dim3(8, 512), 256>>>(x, eWih, ebih, ebhh, 0, 0, 1024);
    enc_rec_kernel<<<128, 256, ENC_SMEM_BYTES>>>(eWhh);
    // x_proj_dec = encoded @ dWih^T + dbih + dbhh : M=65536, N=512, K=256
    proj_kernel<256><<<dim3(4, 512), 256>>>(nullptr, dWih, dbih, dbhh, 1, 1, 512);
    dec_rec_kernel<<<128, 256>>>(dWhh, out);
}